// round 9
// baseline (speedup 1.0000x reference)
#include <cuda_runtime.h>
#include <cstdint>

// BalancedBCE round 7: TMA (cp.async.bulk) HBM->SMEM pipeline, bypassing the
// per-SM LDG/L1tex path that pinned every LDG variant at ~5.1 TB/s.

#define BATCH       64
#define BPB         16                 // chunks per sample -> 1024 CTAs
#define THREADS     256
#define NBLOCKS     (BATCH * BPB)      // 1024
#define STAGE_ELEMS 2048
#define STAGE_BYTES (STAGE_ELEMS * 4)  // 8 KB per array per stage

__device__ float g_part[BPB * 3 * BATCH];   // [blk][qty][b]
__device__ unsigned int g_ticket = 0;

struct __align__(128) SmemLayout {
    float bufx[2][STAGE_ELEMS];
    float buft[2][STAGE_ELEMS];
    unsigned long long full[2];
    unsigned long long empty[2];
};

__device__ __forceinline__ uint32_t sm_u32(const void* p) {
    return (uint32_t)__cvta_generic_to_shared(p);
}
__device__ __forceinline__ void mbar_init(uint32_t a, uint32_t cnt) {
    asm volatile("mbarrier.init.shared.b64 [%0], %1;" :: "r"(a), "r"(cnt) : "memory");
}
__device__ __forceinline__ void mbar_inval(uint32_t a) {
    asm volatile("mbarrier.inval.shared.b64 [%0];" :: "r"(a) : "memory");
}
__device__ __forceinline__ void mbar_expect_tx(uint32_t a, uint32_t bytes) {
    asm volatile("mbarrier.arrive.expect_tx.shared.b64 _, [%0], %1;" :: "r"(a), "r"(bytes) : "memory");
}
__device__ __forceinline__ void mbar_arrive(uint32_t a) {
    asm volatile("mbarrier.arrive.shared.b64 _, [%0];" :: "r"(a) : "memory");
}
__device__ __forceinline__ void mbar_wait(uint32_t a, uint32_t parity) {
    asm volatile(
        "{\n\t"
        ".reg .pred P;\n\t"
        "WAIT_%=: \n\t"
        "mbarrier.try_wait.parity.acquire.cta.shared::cta.b64 P, [%0], %1, 0x989680;\n\t"
        "@P bra DONE_%=;\n\t"
        "bra WAIT_%=;\n\t"
        "DONE_%=: \n\t"
        "}" :: "r"(a), "r"(parity) : "memory");
}
__device__ __forceinline__ void bulk_g2s(uint32_t dst, const void* src,
                                         uint32_t bytes, uint32_t mbar) {
    asm volatile(
        "cp.async.bulk.shared::cluster.global.mbarrier::complete_tx::bytes [%0], [%1], %2, [%3];"
        :: "r"(dst), "l"(src), "r"(bytes), "r"(mbar) : "memory");
}

__device__ __forceinline__ void block_reduce3(float& a, float& b, float& c) {
    #pragma unroll
    for (int off = 16; off > 0; off >>= 1) {
        a += __shfl_down_sync(0xFFFFFFFFu, a, off);
        b += __shfl_down_sync(0xFFFFFFFFu, b, off);
        c += __shfl_down_sync(0xFFFFFFFFu, c, off);
    }
    __shared__ float sa[THREADS / 32], sb[THREADS / 32], sc[THREADS / 32];
    int lane = threadIdx.x & 31;
    int warp = threadIdx.x >> 5;
    if (lane == 0) { sa[warp] = a; sb[warp] = b; sc[warp] = c; }
    __syncthreads();
    if (warp == 0) {
        a = (lane < THREADS / 32) ? sa[lane] : 0.0f;
        b = (lane < THREADS / 32) ? sb[lane] : 0.0f;
        c = (lane < THREADS / 32) ? sc[lane] : 0.0f;
        #pragma unroll
        for (int off = (THREADS / 64); off > 0; off >>= 1) {
            a += __shfl_down_sync(0xFFFFFFFFu, a, off);
            b += __shfl_down_sync(0xFFFFFFFFu, b, off);
            c += __shfl_down_sync(0xFFFFFFFFu, c, off);
        }
    }
}

__global__ void __launch_bounds__(THREADS)
bce_tma_kernel(const float* __restrict__ x_all,
               const float* __restrict__ t_all,
               int n_per_sample,
               float* __restrict__ out)
{
    __shared__ SmemLayout sm;

    const int b   = blockIdx.y;
    const int blk = blockIdx.x;
    const int tid = threadIdx.x;

    const int chunk   = n_per_sample / BPB;          // 16384 for real shape
    const int nstages = chunk / STAGE_ELEMS;         // 8
    const float* __restrict__ xs = x_all + (size_t)b * n_per_sample + (size_t)blk * chunk;
    const float* __restrict__ ts = t_all + (size_t)b * n_per_sample + (size_t)blk * chunk;

    const uint32_t fullA[2]  = { sm_u32(&sm.full[0]),  sm_u32(&sm.full[1]) };
    const uint32_t emptyA[2] = { sm_u32(&sm.empty[0]), sm_u32(&sm.empty[1]) };
    const uint32_t bxA[2]    = { sm_u32(&sm.bufx[0][0]), sm_u32(&sm.bufx[1][0]) };
    const uint32_t btA[2]    = { sm_u32(&sm.buft[0][0]), sm_u32(&sm.buft[1][0]) };

    if (tid == 0) {
        mbar_init(fullA[0], 1);
        mbar_init(fullA[1], 1);
        mbar_init(emptyA[0], THREADS);
        mbar_init(emptyA[1], THREADS);
        asm volatile("fence.proxy.async.shared::cta;" ::: "memory");
    }
    __syncthreads();

    // prologue: fill both buffers
    if (tid == 0) {
        mbar_expect_tx(fullA[0], 2 * STAGE_BYTES);
        bulk_g2s(bxA[0], xs, STAGE_BYTES, fullA[0]);
        bulk_g2s(btA[0], ts, STAGE_BYTES, fullA[0]);
        if (nstages > 1) {
            mbar_expect_tx(fullA[1], 2 * STAGE_BYTES);
            bulk_g2s(bxA[1], xs + STAGE_ELEMS, STAGE_BYTES, fullA[1]);
            bulk_g2s(btA[1], ts + STAGE_ELEMS, STAGE_BYTES, fullA[1]);
        }
    }

    float A = 0.0f, Bp = 0.0f, Cp = 0.0f, cnt = 0.0f;
    float sp_log = 0.0f, sn_log = 0.0f;

    int fp[2] = {0, 0};   // full-barrier parity per buffer
    int ep[2] = {0, 0};   // empty-barrier parity per buffer

    for (int s = 0; s < nstages; s++) {
        const int k = s & 1;
        mbar_wait(fullA[k], fp[k]);
        fp[k] ^= 1;

        const float4* __restrict__ x4 = reinterpret_cast<const float4*>(sm.bufx[k]);
        const float4* __restrict__ t4 = reinterpret_cast<const float4*>(sm.buft[k]);

        float pp = 1.0f, pn = 1.0f;   // 8 factors each, in (1,2] -> <= 256
        #pragma unroll
        for (int q = 0; q < 2; q++) {
            float4 xv = x4[q * THREADS + tid];   // conflict-free LDS.128
            float4 tv = t4[q * THREADS + tid];
            float xarr[4] = {xv.x, xv.y, xv.z, xv.w};
            float tarr[4] = {tv.x, tv.y, tv.z, tv.w};
            #pragma unroll
            for (int kk = 0; kk < 4; kk++) {
                float x = xarr[kk];
                float t = tarr[kk];              // exactly 0.0 or 1.0
                float e = __expf(-fabsf(x));
                float u = t * e;
                pp = fmaf(u, pp, pp);            // *= (1 + t*e)
                pn = fmaf(e - u, pn, pn);        // *= (1 + (1-t)*e)
                float w  = fmaxf(x, 0.0f);
                float wn = fmaxf(-x, 0.0f);
                A   += w;
                Bp   = fmaf(t, wn, Bp);
                Cp   = fmaf(t, w, Cp);
                cnt += t;
            }
        }
        sp_log += __logf(pp);
        sn_log += __logf(pn);

        mbar_arrive(emptyA[k]);

        if (tid == 0 && s + 2 < nstages) {
            mbar_wait(emptyA[k], ep[k]);
            ep[k] ^= 1;
            mbar_expect_tx(fullA[k], 2 * STAGE_BYTES);
            bulk_g2s(bxA[k], xs + (size_t)(s + 2) * STAGE_ELEMS, STAGE_BYTES, fullA[k]);
            bulk_g2s(btA[k], ts + (size_t)(s + 2) * STAGE_ELEMS, STAGE_BYTES, fullA[k]);
        }
    }

    // residual elements (never executes for the real 262144/16/2048 shape)
    for (int i = nstages * STAGE_ELEMS + tid; i < chunk; i += THREADS) {
        float x = xs[i];
        float t = ts[i];
        float e = __expf(-fabsf(x));
        float l = __logf(1.0f + e);
        float w  = fmaxf(x, 0.0f);
        float wn = fmaxf(-x, 0.0f);
        A   += w;
        Bp   = fmaf(t, wn, Bp);
        Cp   = fmaf(t, w, Cp);
        cnt += t;
        sp_log += t * l;
        sn_log += (1.0f - t) * l;
    }

    __syncthreads();          // all stage traffic done before barrier teardown
    if (tid == 0) {
        mbar_inval(fullA[0]);  mbar_inval(fullA[1]);
        mbar_inval(emptyA[0]); mbar_inval(emptyA[1]);
    }

    float sp = Bp + sp_log;
    float sn = (A - Cp) + sn_log;

    block_reduce3(sp, sn, cnt);

    __shared__ bool am_last;
    if (tid == 0) {
        g_part[blk * 192 +   0 + b] = sp;
        g_part[blk * 192 +  64 + b] = sn;
        g_part[blk * 192 + 128 + b] = cnt;
        __threadfence();
        unsigned int tk = atomicAdd(&g_ticket, 1u);
        am_last = (tk == (unsigned)(NBLOCKS - 1));
    }
    __syncthreads();
    if (!am_last) return;

    // ---- last block: final reduction ----
    float wpos = 0.0f, wneg = 0.0f, cpos = 0.0f, cneg = 0.0f;
    if (tid < BATCH) {
        const int bb = tid;
        float Sp = 0.0f, Sn = 0.0f, C = 0.0f;
        #pragma unroll
        for (int j = 0; j < BPB; j++) {
            Sp += g_part[j * 192 +   0 + bb];
            Sn += g_part[j * 192 +  64 + bb];
            C  += g_part[j * 192 + 128 + bb];
        }
        float N     = (float)n_per_sample;
        float tmean = C / N;
        wpos = (1.0f - tmean) * Sp;
        wneg = tmean * Sn;
        cpos = C;
        cneg = N - C;
    }

    __shared__ float s0[2], s1[2], s2[2], s3[2];
    #pragma unroll
    for (int off = 16; off > 0; off >>= 1) {
        wpos += __shfl_down_sync(0xFFFFFFFFu, wpos, off);
        wneg += __shfl_down_sync(0xFFFFFFFFu, wneg, off);
        cpos += __shfl_down_sync(0xFFFFFFFFu, cpos, off);
        cneg += __shfl_down_sync(0xFFFFFFFFu, cneg, off);
    }
    int lane = tid & 31;
    int warp = tid >> 5;
    if (lane == 0 && warp < 2) { s0[warp] = wpos; s1[warp] = wneg; s2[warp] = cpos; s3[warp] = cneg; }
    __syncthreads();
    if (tid == 0) {
        float WP = s0[0] + s0[1];
        float WN = s1[0] + s1[1];
        float CP = s2[0] + s2[1];
        float CN = s3[0] + s3[1];
        out[0] = WP / CP + WN / CN;
        g_ticket = 0;   // reset for next graph replay (deterministic)
    }
}

extern "C" void kernel_launch(void* const* d_in, const int* in_sizes, int n_in,
                              void* d_out, int out_size) {
    const float* x = (const float*)d_in[0];
    const float* t = (const float*)d_in[1];
    float* out = (float*)d_out;

    const int total = in_sizes[0];
    const int n_per_sample = total / BATCH;

    dim3 grid(BPB, BATCH);
    bce_tma_kernel<<<grid, THREADS>>>(x, t, n_per_sample, out);
}

// round 10
// speedup vs baseline: 1.3034x; 1.3034x over previous
#include <cuda_runtime.h>
#include <cuda_bf16.h>

// BalancedBCE round 8 = best LDG kernel (R5) + L1::no_allocate loads.
// Theory: streaming loads that install dead lines in L1 waste L1tex fill
// bandwidth; no_allocate routes L2->RF directly, freeing the per-SM path
// that has pinned every prior variant at ~5.1 TB/s.

#define BATCH   64
#define BPB     19      // 64*19 = 1216 = 8 CTAs x 152 SMs, single balanced wave
#define THREADS 256
#define NBLOCKS (BATCH * BPB)

__device__ float g_part[NBLOCKS * 3];
__device__ unsigned int g_ticket = 0;

__device__ __forceinline__ float4 ldg_na(const float4* p) {
    float4 v;
    asm volatile("ld.global.nc.L1::no_allocate.v4.f32 {%0,%1,%2,%3}, [%4];"
                 : "=f"(v.x), "=f"(v.y), "=f"(v.z), "=f"(v.w)
                 : "l"(p));
    return v;
}

__device__ __forceinline__ void block_reduce3(float& a, float& b, float& c) {
    #pragma unroll
    for (int off = 16; off > 0; off >>= 1) {
        a += __shfl_down_sync(0xFFFFFFFFu, a, off);
        b += __shfl_down_sync(0xFFFFFFFFu, b, off);
        c += __shfl_down_sync(0xFFFFFFFFu, c, off);
    }
    __shared__ float sa[THREADS / 32], sb[THREADS / 32], sc[THREADS / 32];
    int lane = threadIdx.x & 31;
    int warp = threadIdx.x >> 5;
    if (lane == 0) { sa[warp] = a; sb[warp] = b; sc[warp] = c; }
    __syncthreads();
    if (warp == 0) {
        a = (lane < THREADS / 32) ? sa[lane] : 0.0f;
        b = (lane < THREADS / 32) ? sb[lane] : 0.0f;
        c = (lane < THREADS / 32) ? sc[lane] : 0.0f;
        #pragma unroll
        for (int off = (THREADS / 64); off > 0; off >>= 1) {
            a += __shfl_down_sync(0xFFFFFFFFu, a, off);
            b += __shfl_down_sync(0xFFFFFFFFu, b, off);
            c += __shfl_down_sync(0xFFFFFFFFu, c, off);
        }
    }
}

struct Acc {
    float A, Bp, Cp, cnt, sp_log, sn_log;
};

__device__ __forceinline__ void body4(const float4& xv, const float4& tv, Acc& s) {
    float pp = 1.0f, pn = 1.0f;
    float xs[4] = {xv.x, xv.y, xv.z, xv.w};
    float ts[4] = {tv.x, tv.y, tv.z, tv.w};
    #pragma unroll
    for (int k = 0; k < 4; k++) {
        float x = xs[k];
        float t = ts[k];                 // exactly 0.0 or 1.0
        float e = __expf(-fabsf(x));
        float u = t * e;
        pp = fmaf(u, pp, pp);            // pp *= (1 + t*e)
        pn = fmaf(e - u, pn, pn);        // pn *= (1 + (1-t)*e)
        float w  = fmaxf(x, 0.0f);
        float wn = fmaxf(-x, 0.0f);
        s.A   += w;
        s.Bp   = fmaf(t, wn, s.Bp);
        s.Cp   = fmaf(t, w, s.Cp);
        s.cnt += t;
    }
    s.sp_log += __logf(pp);
    s.sn_log += __logf(pn);
}

__global__ void __launch_bounds__(THREADS, 8)
bce_fused_kernel(const float* __restrict__ x_all,
                 const float* __restrict__ t_all,
                 int n_per_sample,
                 float* __restrict__ out)
{
    const int b   = blockIdx.y;
    const int blk = blockIdx.x;

    const float4* __restrict__ x4 =
        reinterpret_cast<const float4*>(x_all + (size_t)b * n_per_sample);
    const float4* __restrict__ t4 =
        reinterpret_cast<const float4*>(t_all + (size_t)b * n_per_sample);
    const int n4 = n_per_sample >> 2;     // 65536 for the real shape
    const int STRIDE = BPB * THREADS;     // 4864

    Acc s = {0.0f, 0.0f, 0.0f, 0.0f, 0.0f, 0.0f};

    int i = blk * THREADS + threadIdx.x;
    // double-step main loop: 4 no-allocate LDG.128 batched up front (MLP 4)
    for (; i + STRIDE < n4; i += 2 * STRIDE) {
        float4 xa = ldg_na(x4 + i);
        float4 xb = ldg_na(x4 + i + STRIDE);
        float4 ta = ldg_na(t4 + i);
        float4 tb = ldg_na(t4 + i + STRIDE);
        body4(xa, ta, s);
        body4(xb, tb, s);
    }
    if (i < n4) {           // ragged tail
        float4 xa = ldg_na(x4 + i);
        float4 ta = ldg_na(t4 + i);
        body4(xa, ta, s);
    }

    float sp = s.Bp + s.sp_log;
    float sn = (s.A - s.Cp) + s.sn_log;
    float cnt = s.cnt;

    block_reduce3(sp, sn, cnt);

    __shared__ bool am_last;
    if (threadIdx.x == 0) {
        g_part[blk * 192 +   0 + b] = sp;
        g_part[blk * 192 +  64 + b] = sn;
        g_part[blk * 192 + 128 + b] = cnt;
        __threadfence();
        unsigned int t = atomicAdd(&g_ticket, 1u);
        am_last = (t == (unsigned)(NBLOCKS - 1));
    }
    __syncthreads();
    if (!am_last) return;

    // ---- last block: final reduction ----
    float wpos = 0.0f, wneg = 0.0f, cpos = 0.0f, cneg = 0.0f;
    if (threadIdx.x < BATCH) {
        const int bb = threadIdx.x;
        float Sp = 0.0f, Sn = 0.0f, C = 0.0f;
        #pragma unroll
        for (int j = 0; j < BPB; j++) {
            Sp += g_part[j * 192 +   0 + bb];
            Sn += g_part[j * 192 +  64 + bb];
            C  += g_part[j * 192 + 128 + bb];
        }
        float N     = (float)n_per_sample;
        float tmean = C / N;
        wpos = (1.0f - tmean) * Sp;
        wneg = tmean * Sn;
        cpos = C;
        cneg = N - C;
    }

    __shared__ float s0[2], s1[2], s2[2], s3[2];
    #pragma unroll
    for (int off = 16; off > 0; off >>= 1) {
        wpos += __shfl_down_sync(0xFFFFFFFFu, wpos, off);
        wneg += __shfl_down_sync(0xFFFFFFFFu, wneg, off);
        cpos += __shfl_down_sync(0xFFFFFFFFu, cpos, off);
        cneg += __shfl_down_sync(0xFFFFFFFFu, cneg, off);
    }
    int lane = threadIdx.x & 31;
    int warp = threadIdx.x >> 5;
    if (lane == 0 && warp < 2) { s0[warp] = wpos; s1[warp] = wneg; s2[warp] = cpos; s3[warp] = cneg; }
    __syncthreads();
    if (threadIdx.x == 0) {
        float WP = s0[0] + s0[1];
        float WN = s1[0] + s1[1];
        float CP = s2[0] + s2[1];
        float CN = s3[0] + s3[1];
        out[0] = WP / CP + WN / CN;
        g_ticket = 0;   // reset for next graph replay (deterministic)
    }
}

extern "C" void kernel_launch(void* const* d_in, const int* in_sizes, int n_in,
                              void* d_out, int out_size) {
    const float* x = (const float*)d_in[0];
    const float* t = (const float*)d_in[1];
    float* out = (float*)d_out;

    const int total = in_sizes[0];
    const int n_per_sample = total / BATCH;

    dim3 grid(BPB, BATCH);
    bce_fused_kernel<<<grid, THREADS>>>(x, t, n_per_sample, out);
}

// round 11
// speedup vs baseline: 1.5333x; 1.1764x over previous
#include <cuda_runtime.h>
#include <cuda_bf16.h>

// BalancedBCE round 9 = R8 (no_allocate, balanced single wave) + L2 prefetch.
// Theory: SM outstanding-LDG capacity (~55-64 entries x 512B ~ 28KB/SM) sits
// exactly at the BW*latency product -> request starvation pins BW at 5.25TB/s.
// prefetch.global.L2 issued one double-step ahead is fire-and-forget: demand
// loads then hit L2 (~4x lower latency), slashing required in-flight bytes.

#define BATCH   64
#define BPB     19      // 64*19 = 1216 = 8 CTAs x 152 SMs, single balanced wave
#define THREADS 256
#define NBLOCKS (BATCH * BPB)

__device__ float g_part[NBLOCKS * 3];
__device__ unsigned int g_ticket = 0;

__device__ __forceinline__ float4 ldg_na(const float4* p) {
    float4 v;
    asm volatile("ld.global.nc.L1::no_allocate.v4.f32 {%0,%1,%2,%3}, [%4];"
                 : "=f"(v.x), "=f"(v.y), "=f"(v.z), "=f"(v.w)
                 : "l"(p));
    return v;
}

__device__ __forceinline__ void pf_l2(const float4* p) {
    asm volatile("prefetch.global.L2 [%0];" :: "l"(p));
}

__device__ __forceinline__ void block_reduce3(float& a, float& b, float& c) {
    #pragma unroll
    for (int off = 16; off > 0; off >>= 1) {
        a += __shfl_down_sync(0xFFFFFFFFu, a, off);
        b += __shfl_down_sync(0xFFFFFFFFu, b, off);
        c += __shfl_down_sync(0xFFFFFFFFu, c, off);
    }
    __shared__ float sa[THREADS / 32], sb[THREADS / 32], sc[THREADS / 32];
    int lane = threadIdx.x & 31;
    int warp = threadIdx.x >> 5;
    if (lane == 0) { sa[warp] = a; sb[warp] = b; sc[warp] = c; }
    __syncthreads();
    if (warp == 0) {
        a = (lane < THREADS / 32) ? sa[lane] : 0.0f;
        b = (lane < THREADS / 32) ? sb[lane] : 0.0f;
        c = (lane < THREADS / 32) ? sc[lane] : 0.0f;
        #pragma unroll
        for (int off = (THREADS / 64); off > 0; off >>= 1) {
            a += __shfl_down_sync(0xFFFFFFFFu, a, off);
            b += __shfl_down_sync(0xFFFFFFFFu, b, off);
            c += __shfl_down_sync(0xFFFFFFFFu, c, off);
        }
    }
}

struct Acc {
    float A, Bp, Cp, cnt, sp_log, sn_log;
};

__device__ __forceinline__ void body4(const float4& xv, const float4& tv, Acc& s) {
    float pp = 1.0f, pn = 1.0f;
    float xs[4] = {xv.x, xv.y, xv.z, xv.w};
    float ts[4] = {tv.x, tv.y, tv.z, tv.w};
    #pragma unroll
    for (int k = 0; k < 4; k++) {
        float x = xs[k];
        float t = ts[k];                 // exactly 0.0 or 1.0
        float e = __expf(-fabsf(x));
        float u = t * e;
        pp = fmaf(u, pp, pp);            // pp *= (1 + t*e)
        pn = fmaf(e - u, pn, pn);        // pn *= (1 + (1-t)*e)
        float w  = fmaxf(x, 0.0f);
        float wn = fmaxf(-x, 0.0f);
        s.A   += w;
        s.Bp   = fmaf(t, wn, s.Bp);
        s.Cp   = fmaf(t, w, s.Cp);
        s.cnt += t;
    }
    s.sp_log += __logf(pp);
    s.sn_log += __logf(pn);
}

__global__ void __launch_bounds__(THREADS, 8)
bce_fused_kernel(const float* __restrict__ x_all,
                 const float* __restrict__ t_all,
                 int n_per_sample,
                 float* __restrict__ out)
{
    const int b   = blockIdx.y;
    const int blk = blockIdx.x;

    const float4* __restrict__ x4 =
        reinterpret_cast<const float4*>(x_all + (size_t)b * n_per_sample);
    const float4* __restrict__ t4 =
        reinterpret_cast<const float4*>(t_all + (size_t)b * n_per_sample);
    const int n4 = n_per_sample >> 2;     // 65536 for the real shape
    const int STRIDE = BPB * THREADS;     // 4864

    Acc s = {0.0f, 0.0f, 0.0f, 0.0f, 0.0f, 0.0f};

    const bool pf_lane = ((threadIdx.x & 7) == 0);   // 1 prefetch per 128B line

    int i = blk * THREADS + threadIdx.x;
    // warm the prefetch pipeline: next double-step's lines
    if (pf_lane) {
        int p0 = min(i + 2 * STRIDE, n4 - 1);
        int p1 = min(i + 3 * STRIDE, n4 - 1);
        pf_l2(x4 + p0); pf_l2(t4 + p0);
        pf_l2(x4 + p1); pf_l2(t4 + p1);
    }

    for (; i + STRIDE < n4; i += 2 * STRIDE) {
        if (pf_lane) {                    // prefetch one double-step ahead
            int p0 = min(i + 4 * STRIDE, n4 - 1);
            int p1 = min(i + 5 * STRIDE, n4 - 1);
            pf_l2(x4 + p0); pf_l2(t4 + p0);
            pf_l2(x4 + p1); pf_l2(t4 + p1);
        }
        float4 xa = ldg_na(x4 + i);
        float4 xb = ldg_na(x4 + i + STRIDE);
        float4 ta = ldg_na(t4 + i);
        float4 tb = ldg_na(t4 + i + STRIDE);
        body4(xa, ta, s);
        body4(xb, tb, s);
    }
    if (i < n4) {           // ragged tail
        float4 xa = ldg_na(x4 + i);
        float4 ta = ldg_na(t4 + i);
        body4(xa, ta, s);
    }

    float sp = s.Bp + s.sp_log;
    float sn = (s.A - s.Cp) + s.sn_log;
    float cnt = s.cnt;

    block_reduce3(sp, sn, cnt);

    __shared__ bool am_last;
    if (threadIdx.x == 0) {
        g_part[blk * 192 +   0 + b] = sp;
        g_part[blk * 192 +  64 + b] = sn;
        g_part[blk * 192 + 128 + b] = cnt;
        __threadfence();
        unsigned int t = atomicAdd(&g_ticket, 1u);
        am_last = (t == (unsigned)(NBLOCKS - 1));
    }
    __syncthreads();
    if (!am_last) return;

    // ---- last block: final reduction ----
    float wpos = 0.0f, wneg = 0.0f, cpos = 0.0f, cneg = 0.0f;
    if (threadIdx.x < BATCH) {
        const int bb = threadIdx.x;
        float Sp = 0.0f, Sn = 0.0f, C = 0.0f;
        #pragma unroll
        for (int j = 0; j < BPB; j++) {
            Sp += g_part[j * 192 +   0 + bb];
            Sn += g_part[j * 192 +  64 + bb];
            C  += g_part[j * 192 + 128 + bb];
        }
        float N     = (float)n_per_sample;
        float tmean = C / N;
        wpos = (1.0f - tmean) * Sp;
        wneg = tmean * Sn;
        cpos = C;
        cneg = N - C;
    }

    __shared__ float s0[2], s1[2], s2[2], s3[2];
    #pragma unroll
    for (int off = 16; off > 0; off >>= 1) {
        wpos += __shfl_down_sync(0xFFFFFFFFu, wpos, off);
        wneg += __shfl_down_sync(0xFFFFFFFFu, wneg, off);
        cpos += __shfl_down_sync(0xFFFFFFFFu, cpos, off);
        cneg += __shfl_down_sync(0xFFFFFFFFu, cneg, off);
    }
    int lane = threadIdx.x & 31;
    int warp = threadIdx.x >> 5;
    if (lane == 0 && warp < 2) { s0[warp] = wpos; s1[warp] = wneg; s2[warp] = cpos; s3[warp] = cneg; }
    __syncthreads();
    if (threadIdx.x == 0) {
        float WP = s0[0] + s0[1];
        float WN = s1[0] + s1[1];
        float CP = s2[0] + s2[1];
        float CN = s3[0] + s3[1];
        out[0] = WP / CP + WN / CN;
        g_ticket = 0;   // reset for next graph replay (deterministic)
    }
}

extern "C" void kernel_launch(void* const* d_in, const int* in_sizes, int n_in,
                              void* d_out, int out_size) {
    const float* x = (const float*)d_in[0];
    const float* t = (const float*)d_in[1];
    float* out = (float*)d_out;

    const int total = in_sizes[0];
    const int n_per_sample = total / BATCH;

    dim3 grid(BPB, BATCH);
    bce_fused_kernel<<<grid, THREADS>>>(x, t, n_per_sample, out);
}